// round 6
// baseline (speedup 1.0000x reference)
#include <cuda_runtime.h>
#include <cuda_bf16.h>
#include <math.h>
#include <stdint.h>

// Problem constants: B=64, T=512, V=32000, E=256, H=512, 4H=2048, NT=12, C=10
#define NBLK 128          // persistent LSTM blocks (<=148 SMs -> co-resident)
#define PADTAG 0
#define BOS 10
#define EOSx 11

// ---------------- scratch: static device memory (no runtime allocs) ----------
__device__ float    g_X[2][67108864];      // [dir][(b*512+t)*2048 + g*512+u] (NO bias)
__device__ float    g_hid[33554432];       // [((t*64+b)*2 + dir)*512 + u]
__device__ float    g_h[2 * 3 * 512 * 64]; // [dir][buf][u][b]  carry ring
__device__ float    g_hT[64 * 1024];       // [b][dir*512+u] final carry
__device__ float    g_emis[32768 * 12];    // [(t*64+b)*12 + tag]
__device__ unsigned g_bar;

// ---------------- XLA-exact activations --------------------------------------
// Matches XLA EmitFastTanh (Eigen rational approx, clamp +-9, |x|<4e-4 -> x),
// used by both XLA:CPU and XLA:GPU for f32 tanh. Sigmoid matches XLA's
// logistic expansion: 0.5 + 0.5*tanh(0.5*x). All ops are explicit _rn
// intrinsics so no FMA contraction / fast-math flag can change the rounding.
__device__ __forceinline__ float tanh_xla(float x) {
    const float ax = fabsf(x);
    float xc = fminf(fmaxf(x, -9.0f), 9.0f);
    float x2 = __fmul_rn(xc, xc);
    float p = -2.76076847742355e-16f;
    p = __fadd_rn(__fmul_rn(x2, p),  2.00018790482477e-13f);
    p = __fadd_rn(__fmul_rn(x2, p), -8.60467152213735e-11f);
    p = __fadd_rn(__fmul_rn(x2, p),  5.12229709037114e-08f);
    p = __fadd_rn(__fmul_rn(x2, p),  1.48572235717979e-05f);
    p = __fadd_rn(__fmul_rn(x2, p),  6.37261928875436e-04f);
    p = __fadd_rn(__fmul_rn(x2, p),  4.89352455891786e-03f);
    float num = __fmul_rn(xc, p);
    float q = 1.19825839466702e-06f;
    q = __fadd_rn(__fmul_rn(x2, q), 1.18534705686654e-04f);
    q = __fadd_rn(__fmul_rn(x2, q), 2.26843463243900e-03f);
    q = __fadd_rn(__fmul_rn(x2, q), 4.89352518554385e-03f);
    float r = __fdiv_rn(num, q);
    return (ax < 0.0004f) ? x : r;
}
__device__ __forceinline__ float sigmoid_xla(float x) {
    return __fadd_rn(0.5f, __fmul_rn(0.5f, tanh_xla(__fmul_rn(0.5f, x))));
}

// ---------------- init: reset spin-barrier counter every replay --------------
__global__ void init_kernel() { if (threadIdx.x == 0) g_bar = 0u; }

// ---------------- phase 1: fused embedding gather + input projection GEMM ----
// out[m][n] = emb[x[m]] . W[n][:]   (bias added later in lstm, matching the
// reference's (A+B)+b association).  m = b*512+t == flat x index.
__global__ __launch_bounds__(256) void gemm_ih(const int* __restrict__ x,
                                               const float* __restrict__ emb,
                                               const float* __restrict__ wf,
                                               const float* __restrict__ wb) {
    __shared__ float As[16][64];
    __shared__ float Bs[16][64];
    __shared__ int   rix[64];
    const int dir = blockIdx.z;
    const float* __restrict__ W = dir ? wb : wf;
    float* __restrict__ Xout = g_X[dir];
    const int tid = threadIdx.x;
    const int m0 = blockIdx.y << 6, n0 = blockIdx.x << 6;

    if (tid < 64) rix[tid] = x[m0 + tid];
    __syncthreads();

    const int r  = tid & 63, kk = tid >> 6;       // loader: row r, k-quad kk
    const int tx = tid & 15, ty = tid >> 4;       // compute: 4x4 micro-tile
    const float* aptr = emb + (size_t)rix[r] * 256 + (kk << 2);
    const float* bptr = W   + (size_t)(n0 + r) * 256 + (kk << 2);

    float acc[4][4];
#pragma unroll
    for (int i = 0; i < 4; ++i)
#pragma unroll
        for (int j = 0; j < 4; ++j) acc[i][j] = 0.f;

    for (int kt = 0; kt < 16; ++kt) {
        float4 a = *(const float4*)(aptr + (kt << 4));
        float4 b = *(const float4*)(bptr + (kt << 4));
        __syncthreads();
        As[(kk << 2) + 0][r] = a.x; As[(kk << 2) + 1][r] = a.y;
        As[(kk << 2) + 2][r] = a.z; As[(kk << 2) + 3][r] = a.w;
        Bs[(kk << 2) + 0][r] = b.x; Bs[(kk << 2) + 1][r] = b.y;
        Bs[(kk << 2) + 2][r] = b.z; Bs[(kk << 2) + 3][r] = b.w;
        __syncthreads();
#pragma unroll
        for (int k = 0; k < 16; ++k) {
            float4 av = *(const float4*)&As[k][ty << 2];
            float4 bv = *(const float4*)&Bs[k][tx << 2];
            float ar[4] = {av.x, av.y, av.z, av.w};
            float br[4] = {bv.x, bv.y, bv.z, bv.w};
#pragma unroll
            for (int i = 0; i < 4; ++i)
#pragma unroll
                for (int j = 0; j < 4; ++j)
                    acc[i][j] = fmaf(ar[i], br[j], acc[i][j]);
        }
    }
#pragma unroll
    for (int i = 0; i < 4; ++i) {
        size_t m = (size_t)(m0 + (ty << 2) + i);
        float4 s = make_float4(acc[i][0], acc[i][1], acc[i][2], acc[i][3]);
        *(float4*)(Xout + m * 2048 + n0 + (tx << 2)) = s;
    }
}

// ---------------- phase 2: persistent bidirectional LSTM ---------------------
// 128 blocks. dir = blk/64; block owns 8 hidden units u0 = (blk%64)*8.
// Smem: Wsm 32x512 (its 32 w_hh rows), hsm[k][b] 512x64 (full carry, k-major),
// csm 8x64 (its cell state). Carry h rotates through 3 L2 buffers; one grid
// barrier per step (3-buffer ring removes the ping-pong WAR hazard).
#define LSTM_SMEM ((32 * 512 + 512 * 64 + 512) * 4)

__device__ __forceinline__ void grid_barrier(unsigned target) {
    __syncthreads();
    if (threadIdx.x == 0) {
        __threadfence();
        atomicAdd(&g_bar, 1u);
        while (*(volatile unsigned*)&g_bar < target) __nanosleep(64);
        __threadfence();
    }
    __syncthreads();
}

__global__ __launch_bounds__(256, 1) void lstm_kernel(const int* __restrict__ x,
                                                      const float* __restrict__ whh_f,
                                                      const float* __restrict__ whh_b,
                                                      const float* __restrict__ bias_f,
                                                      const float* __restrict__ bias_b) {
    extern __shared__ float sm[];
    float* Wsm = sm;                       // 32*512
    float* hsm = sm + 32 * 512;            // 512*64 (k-major: [k*64+b])
    float* csm = hsm + 512 * 64;           // 8*64   ([j*64+b])

    const int tid = threadIdx.x;
    const int blk = blockIdx.x;
    const int dir = blk >> 6;
    const int u0  = (blk & 63) << 3;
    const int b   = tid & 63;
    const int p   = tid >> 6;              // 0..3; this thread owns units p, p+4
    const float* __restrict__ Whh = dir ? whh_b : whh_f;
    const float* __restrict__ bia = dir ? bias_b : bias_f;
    const float* __restrict__ Xg  = g_X[dir];
    float* __restrict__ ring = g_h + dir * (3 * 512 * 64);

    // resident weights: local row lr = gate*8 + j  ->  w_hh[gate*512+u0+j][:]
    for (int i = tid; i < 32 * 128; i += 256) {     // float4 granules
        int lr = i >> 7, k4 = (i & 127) << 2;
        int gate = lr >> 3, j = lr & 7;
        float4 v = *(const float4*)&Whh[(size_t)(gate * 512 + u0 + j) * 512 + k4];
        *(float4*)&Wsm[lr * 512 + k4] = v;
    }
    // per-thread biases for its 2 units x 4 gates
    float bb0[4], bb1[4];
#pragma unroll
    for (int g = 0; g < 4; ++g) {
        bb0[g] = bia[g * 512 + u0 + p];
        bb1[g] = bia[g * 512 + u0 + p + 4];
    }
    for (int i = tid; i < 512; i += 256) csm[i] = 0.f;
    // zero buffer 0 for own units
    for (int i = tid; i < 512; i += 256)
        ring[(0 * 512 + u0 + (i >> 6)) * 64 + (i & 63)] = 0.f;
    __threadfence();
    unsigned nbar = 1;
    grid_barrier(nbar * NBLK);

    for (int s = 0; s < 512; ++s) {
        const int t  = dir ? 511 - s : s;
        const int rb = s % 3, wbuf = (s + 1) % 3;

        // stage full carry h into smem (L2 reads; layouts match: [u][b]==[k][b])
        const float* src = ring + rb * (512 * 64);
        for (int i = tid << 2; i < 32768; i += 1024)
            *(float4*)&hsm[i] = __ldcg((const float4*)(src + i));
        __syncthreads();

        // 8 dot products of length 512 per thread (2 units x 4 gates)
        float d0[4] = {0.f, 0.f, 0.f, 0.f};
        float d1[4] = {0.f, 0.f, 0.f, 0.f};
        for (int k = 0; k < 512; k += 4) {
            float h0 = hsm[(k + 0) * 64 + b];
            float h1 = hsm[(k + 1) * 64 + b];
            float h2 = hsm[(k + 2) * 64 + b];
            float h3 = hsm[(k + 3) * 64 + b];
#pragma unroll
            for (int g = 0; g < 4; ++g) {
                float4 w0 = *(const float4*)&Wsm[(g * 8 + p) * 512 + k];
                d0[g] = fmaf(h0, w0.x, fmaf(h1, w0.y, fmaf(h2, w0.z, fmaf(h3, w0.w, d0[g]))));
                float4 w1 = *(const float4*)&Wsm[(g * 8 + p + 4) * 512 + k];
                d1[g] = fmaf(h0, w1.x, fmaf(h1, w1.y, fmaf(h2, w1.z, fmaf(h3, w1.w, d1[g]))));
            }
        }

        const bool mk = (x[b * 512 + t] != 0);
#pragma unroll
        for (int half = 0; half < 2; ++half) {
            const float* dd = half ? d1 : d0;
            const float* bv = half ? bb1 : bb0;
            const int j = p + half * 4;
            const int u = u0 + j;
            const size_t xb = ((size_t)b * 512 + t) * 2048 + u;
            // reference association: z = (x-part + h-part) + bias, exact _rn ops
            float zi = __fadd_rn(__fadd_rn(Xg[xb],          dd[0]), bv[0]);
            float zf = __fadd_rn(__fadd_rn(Xg[xb + 512],    dd[1]), bv[1]);
            float zg = __fadd_rn(__fadd_rn(Xg[xb + 1024],   dd[2]), bv[2]);
            float zo = __fadd_rn(__fadd_rn(Xg[xb + 1536],   dd[3]), bv[3]);
            float ii = sigmoid_xla(zi);
            float ff = sigmoid_xla(zf);
            float oo = sigmoid_xla(zo);
            float gg = tanh_xla(zg);
            float cold = csm[j * 64 + b];
            // c_new = (f*c) + (i*g), no contraction
            float cn = __fadd_rn(__fmul_rn(ff, cold), __fmul_rn(ii, gg));
            float hn = __fmul_rn(oo, tanh_xla(cn));
            float hold = hsm[u * 64 + b];
            float ck = mk ? cn : cold;
            float hk = mk ? hn : hold;
            csm[j * 64 + b] = ck;
            g_hid[((size_t)(t * 64 + b) * 2 + dir) * 512 + u] = mk ? hn : 0.f;
            ring[(wbuf * 512 + u) * 64 + b] = hk;
            if (s == 511) g_hT[b * 1024 + dir * 512 + u] = hk;
        }
        __threadfence();
        ++nbar;
        grid_barrier(nbar * NBLK);
    }
}

// ---------------- phase 3: emissions = hid @ fc_w.T + fc_b -------------------
// fp64 accumulation: our dot is then correctly rounded, so |ours - ref| is
// bounded by the reference's own fp32 rounding noise.
__global__ __launch_bounds__(256) void emis_kernel(const float* __restrict__ fcw,
                                                   const float* __restrict__ fcb) {
    const int warp = (blockIdx.x * 256 + threadIdx.x) >> 5;
    const int lane = threadIdx.x & 31;
    if (warp >= 32768) return;
    const float* hrow = g_hid + (size_t)warp * 1024;
    double acc[12];
#pragma unroll
    for (int j = 0; j < 12; ++j) acc[j] = 0.0;
    for (int k = lane; k < 1024; k += 32) {
        double hv = (double)hrow[k];
#pragma unroll
        for (int j = 0; j < 12; ++j)
            acc[j] = fma(hv, (double)__ldg(&fcw[j * 1024 + k]), acc[j]);
    }
#pragma unroll
    for (int j = 0; j < 12; ++j)
#pragma unroll
        for (int off = 16; off; off >>= 1)
            acc[j] += __shfl_down_sync(0xffffffffu, acc[j], off);
    if (lane == 0) {
#pragma unroll
        for (int j = 0; j < 12; ++j)
            g_emis[(size_t)warp * 12 + j] = __fadd_rn((float)acc[j], fcb[j]);
    }
}

// ---------------- phase 4: class probs = softmax(hT @ fc2_w.T + fc2_b) -------
__global__ __launch_bounds__(32) void cls_kernel(const float* __restrict__ w2,
                                                 const float* __restrict__ b2,
                                                 float* __restrict__ out) {
    const int bb = blockIdx.x;
    const int lane = threadIdx.x;
    double acc[10];
#pragma unroll
    for (int j = 0; j < 10; ++j) acc[j] = 0.0;
    for (int k = lane; k < 1024; k += 32) {
        double hv = (double)g_hT[bb * 1024 + k];
#pragma unroll
        for (int j = 0; j < 10; ++j)
            acc[j] = fma(hv, (double)__ldg(&w2[j * 1024 + k]), acc[j]);
    }
#pragma unroll
    for (int j = 0; j < 10; ++j)
#pragma unroll
        for (int off = 16; off; off >>= 1)
            acc[j] += __shfl_down_sync(0xffffffffu, acc[j], off);
    if (lane == 0) {
        float z[10], mx = -1e30f, ssum = 0.f;
#pragma unroll
        for (int j = 0; j < 10; ++j) { z[j] = __fadd_rn((float)acc[j], b2[j]); mx = fmaxf(mx, z[j]); }
#pragma unroll
        for (int j = 0; j < 10; ++j) { z[j] = expf(z[j] - mx); ssum += z[j]; }
        float inv = 1.f / ssum;
#pragma unroll
        for (int j = 0; j < 10; ++j) out[64 + 32768 + bb * 10 + j] = z[j] * inv;
    }
}

// ---------------- phase 5: Viterbi (per-batch, all state in smem) ------------
__global__ __launch_bounds__(32) void vit_kernel(const int* __restrict__ x,
                                                 const float* __restrict__ trans,
                                                 float* __restrict__ out) {
    const int bb = blockIdx.x;
    const int lane = threadIdx.x;
    __shared__ float tr[144];
    __shared__ float alph[12];
    __shared__ short bp[511][12];
    __shared__ short path[512];

    for (int i = lane; i < 144; i += 32) tr[i] = trans[i];
    __syncthreads();
    if (lane < 12)
        alph[lane] = __fadd_rn(tr[BOS * 12 + lane],
                               g_emis[(size_t)(0 * 64 + bb) * 12 + lane]);
    __syncthreads();

    for (int t = 1; t < 512; ++t) {
        float na = 0.f; short nb = 0;
        const int valid = (x[bb * 512 + t] != 0);
        if (lane < 12) {
            float e = g_emis[(size_t)(t * 64 + bb) * 12 + lane];
            float best = -1e30f; int bi = 0;
#pragma unroll
            for (int i = 0; i < 12; ++i) {
                float sc = __fadd_rn(alph[i], tr[i * 12 + lane]);
                if (sc > best) { best = sc; bi = i; }   // first-index tie-break
            }
            na = valid ? __fadd_rn(best, e) : alph[lane];
            nb = valid ? (short)bi : (short)lane;
        }
        __syncthreads();
        if (lane < 12) { alph[lane] = na; bp[t - 1][lane] = nb; }
        __syncthreads();
    }

    if (lane == 0) {
        float best = -1e30f; int bt = 0;
#pragma unroll
        for (int j = 0; j < 12; ++j) {
            float f = __fadd_rn(alph[j], tr[j * 12 + EOSx]);
            if (f > best) { best = f; bt = j; }
        }
        out[bb] = best;
        int tag = bt;
        for (int t = 511; t >= 1; --t) { path[t] = (short)tag; tag = bp[t - 1][tag]; }
        path[0] = (short)tag;
    }
    __syncthreads();
    for (int t = lane; t < 512; t += 32)
        out[64 + bb * 512 + t] = (x[bb * 512 + t] != 0) ? (float)path[t] : (float)PADTAG;
}

// ---------------- launcher ---------------------------------------------------
extern "C" void kernel_launch(void* const* d_in, const int* in_sizes, int n_in,
                              void* d_out, int out_size) {
    const int*   x      = (const int*)d_in[0];
    const float* emb    = (const float*)d_in[1];
    const float* w_ih_f = (const float*)d_in[2];
    const float* w_hh_f = (const float*)d_in[3];
    const float* b_f    = (const float*)d_in[4];
    const float* w_ih_b = (const float*)d_in[5];
    const float* w_hh_b = (const float*)d_in[6];
    const float* b_b    = (const float*)d_in[7];
    const float* fc_w   = (const float*)d_in[8];
    const float* fc_b   = (const float*)d_in[9];
    const float* fc2_w  = (const float*)d_in[10];
    const float* fc2_b  = (const float*)d_in[11];
    const float* trans  = (const float*)d_in[12];
    float* out = (float*)d_out;

    cudaFuncSetAttribute(lstm_kernel,
                         cudaFuncAttributeMaxDynamicSharedMemorySize, LSTM_SMEM);

    init_kernel<<<1, 32>>>();
    gemm_ih<<<dim3(32, 512, 2), 256>>>(x, emb, w_ih_f, w_ih_b);
    lstm_kernel<<<NBLK, 256, LSTM_SMEM>>>(x, w_hh_f, w_hh_b, b_f, b_b);
    emis_kernel<<<4096, 256>>>(fc_w, fc_b);
    cls_kernel<<<64, 32>>>(fc2_w, fc2_b, out);
    vit_kernel<<<64, 32>>>(x, trans, out);
}

// round 9
// speedup vs baseline: 1.1294x; 1.1294x over previous
#include <cuda_runtime.h>
#include <cuda_bf16.h>
#include <math.h>
#include <stdint.h>

// Problem constants: B=64, T=512, V=32000, E=256, H=512, 4H=2048, NT=12, C=10
#define NBLK 128          // persistent LSTM blocks (<=148 SMs -> co-resident)
#define PADTAG 0
#define BOS 10
#define EOSx 11

// ---------------- scratch: static device memory (no runtime allocs) ----------
__device__ float    g_X[2][67108864];      // [dir][(b*512+t)*2048 + g*512+u] (NO bias)
__device__ float    g_hid[33554432];       // [((t*64+b)*2 + dir)*512 + u]
__device__ float    g_h[2 * 3 * 512 * 64]; // [dir][buf][k2][b] float2-packed carry ring
__device__ float    g_hT[64 * 1024];       // [b][dir*512+u] final carry
__device__ float    g_emis[32768 * 12];    // [(t*64+b)*12 + tag]
__device__ unsigned g_bar;

// ---------------- f32x2 packed-FMA helpers (sm_103a) -------------------------
union U64F2 { unsigned long long u; float2 f2; };
union F4U2  { float4 f4; unsigned long long u2[2]; };

__device__ __forceinline__ unsigned long long fma2(unsigned long long a,
                                                   unsigned long long b,
                                                   unsigned long long c) {
    unsigned long long d;
    asm("fma.rn.f32x2 %0, %1, %2, %3;" : "=l"(d) : "l"(a), "l"(b), "l"(c));
    return d;
}
__device__ __forceinline__ unsigned long long splat2(float a) {
    unsigned long long r;
    asm("mov.b64 %0, {%1, %1};" : "=l"(r) : "f"(a));
    return r;
}

// ---------------- XLA-exact activations --------------------------------------
__device__ __forceinline__ float tanh_xla(float x) {
    const float ax = fabsf(x);
    float xc = fminf(fmaxf(x, -9.0f), 9.0f);
    float x2 = __fmul_rn(xc, xc);
    float p = -2.76076847742355e-16f;
    p = __fadd_rn(__fmul_rn(x2, p),  2.00018790482477e-13f);
    p = __fadd_rn(__fmul_rn(x2, p), -8.60467152213735e-11f);
    p = __fadd_rn(__fmul_rn(x2, p),  5.12229709037114e-08f);
    p = __fadd_rn(__fmul_rn(x2, p),  1.48572235717979e-05f);
    p = __fadd_rn(__fmul_rn(x2, p),  6.37261928875436e-04f);
    p = __fadd_rn(__fmul_rn(x2, p),  4.89352455891786e-03f);
    float num = __fmul_rn(xc, p);
    float q = 1.19825839466702e-06f;
    q = __fadd_rn(__fmul_rn(x2, q), 1.18534705686654e-04f);
    q = __fadd_rn(__fmul_rn(x2, q), 2.26843463243900e-03f);
    q = __fadd_rn(__fmul_rn(x2, q), 4.89352518554385e-03f);
    float r = __fdiv_rn(num, q);
    return (ax < 0.0004f) ? x : r;
}
__device__ __forceinline__ float sigmoid_xla(float x) {
    return __fadd_rn(0.5f, __fmul_rn(0.5f, tanh_xla(__fmul_rn(0.5f, x))));
}

// ---------------- init: reset spin-barrier counter every replay --------------
__global__ void init_kernel() { if (threadIdx.x == 0) g_bar = 0u; }

// ---------------- phase 1: fused embedding gather + input projection GEMM ----
// out[m][n] = emb[x[m]] . W[n][:]  (bias added in lstm). Packed f32x2 over
// output-column pairs: each accumulator's k-chain is bit-identical to scalar.
__global__ __launch_bounds__(256) void gemm_ih(const int* __restrict__ x,
                                               const float* __restrict__ emb,
                                               const float* __restrict__ wf,
                                               const float* __restrict__ wb) {
    __shared__ float As[16][64];
    __shared__ float Bs[16][64];
    __shared__ int   rix[64];
    const int dir = blockIdx.z;
    const float* __restrict__ W = dir ? wb : wf;
    float* __restrict__ Xout = g_X[dir];
    const int tid = threadIdx.x;
    const int m0 = blockIdx.y << 6, n0 = blockIdx.x << 6;

    if (tid < 64) rix[tid] = x[m0 + tid];
    __syncthreads();

    const int r  = tid & 63, kk = tid >> 6;       // loader: row r, k-quad kk
    const int tx = tid & 15, ty = tid >> 4;       // compute: 4x4 micro-tile
    const float* aptr = emb + (size_t)rix[r] * 256 + (kk << 2);
    const float* bptr = W   + (size_t)(n0 + r) * 256 + (kk << 2);

    unsigned long long acc[4][2];
#pragma unroll
    for (int i = 0; i < 4; ++i) { acc[i][0] = 0ull; acc[i][1] = 0ull; }

    for (int kt = 0; kt < 16; ++kt) {
        float4 a = *(const float4*)(aptr + (kt << 4));
        float4 b = *(const float4*)(bptr + (kt << 4));
        __syncthreads();
        As[(kk << 2) + 0][r] = a.x; As[(kk << 2) + 1][r] = a.y;
        As[(kk << 2) + 2][r] = a.z; As[(kk << 2) + 3][r] = a.w;
        Bs[(kk << 2) + 0][r] = b.x; Bs[(kk << 2) + 1][r] = b.y;
        Bs[(kk << 2) + 2][r] = b.z; Bs[(kk << 2) + 3][r] = b.w;
        __syncthreads();
#pragma unroll
        for (int k = 0; k < 16; ++k) {
            float4 av = *(const float4*)&As[k][ty << 2];
            F4U2 bu; bu.f4 = *(const float4*)&Bs[k][tx << 2];
            float ar[4] = {av.x, av.y, av.z, av.w};
#pragma unroll
            for (int i = 0; i < 4; ++i) {
                unsigned long long ai = splat2(ar[i]);
                acc[i][0] = fma2(ai, bu.u2[0], acc[i][0]);
                acc[i][1] = fma2(ai, bu.u2[1], acc[i][1]);
            }
        }
    }
#pragma unroll
    for (int i = 0; i < 4; ++i) {
        size_t m = (size_t)(m0 + (ty << 2) + i);
        U64F2 lo, hi; lo.u = acc[i][0]; hi.u = acc[i][1];
        float4 s = make_float4(lo.f2.x, lo.f2.y, hi.f2.x, hi.f2.y);
        *(float4*)(Xout + m * 2048 + n0 + (tx << 2)) = s;
    }
}

// ---------------- phase 2: persistent bidirectional LSTM ---------------------
// 128 blocks. dir = blk/64; block owns 8 hidden units u0 = (blk%64)*8.
// h carry is float2-packed [k2][b]; staging is a 4-chunk LDG->STS pipeline
// overlapping the L2 reads with the packed-FMA dot products.
#define LSTM_SMEM ((32 * 512 + 512 * 64 + 512) * 4)

__device__ __forceinline__ void grid_barrier(unsigned target) {
    __syncthreads();
    if (threadIdx.x == 0) {
        __threadfence();
        atomicAdd(&g_bar, 1u);
        while (*(volatile unsigned*)&g_bar < target) __nanosleep(64);
        __threadfence();
    }
    __syncthreads();
}

__global__ __launch_bounds__(256, 1) void lstm_kernel(const int* __restrict__ x,
                                                      const float* __restrict__ whh_f,
                                                      const float* __restrict__ whh_b,
                                                      const float* __restrict__ bias_f,
                                                      const float* __restrict__ bias_b) {
    extern __shared__ float sm[];
    float* Wsm = sm;                       // 32*512
    float* hsm = sm + 32 * 512;            // packed [k2][b] float2 (512*64 floats)
    float* csm = hsm + 512 * 64;           // 8*64   ([j*64+b])

    const int tid = threadIdx.x;
    const int blk = blockIdx.x;
    const int dir = blk >> 6;
    const int u0  = (blk & 63) << 3;
    const int b   = tid & 63;
    const int p   = tid >> 6;              // 0..3; thread owns units p, p+4
    const float* __restrict__ Whh = dir ? whh_b : whh_f;
    const float* __restrict__ bia = dir ? bias_b : bias_f;
    const float* __restrict__ Xg  = g_X[dir];
    float* __restrict__ ring = g_h + dir * (3 * 512 * 64);

    // resident weights: local row lr = gate*8 + j  ->  w_hh[gate*512+u0+j][:]
    for (int i = tid; i < 32 * 128; i += 256) {     // float4 granules
        int lr = i >> 7, k4 = (i & 127) << 2;
        int gate = lr >> 3, j = lr & 7;
        float4 v = *(const float4*)&Whh[(size_t)(gate * 512 + u0 + j) * 512 + k4];
        *(float4*)&Wsm[lr * 512 + k4] = v;
    }
    float bb0[4], bb1[4];
#pragma unroll
    for (int g = 0; g < 4; ++g) {
        bb0[g] = bia[g * 512 + u0 + p];
        bb1[g] = bia[g * 512 + u0 + p + 4];
    }
    for (int i = tid; i < 512; i += 256) csm[i] = 0.f;
    // zero ring buffer 0 for own units (packed layout)
    for (int i = tid; i < 512; i += 256) {
        int j = i >> 6, bb = i & 63, u = u0 + j;
        ring[((u >> 1) * 64 + bb) * 2 + (u & 1)] = 0.f;
    }
    __threadfence();
    unsigned nbar = 1;
    grid_barrier(nbar * NBLK);

    for (int s = 0; s < 512; ++s) {
        const int t  = dir ? 511 - s : s;
        const int rb = s % 3, wbuf = (s + 1) % 3;

        const float4* src4 = (const float4*)(ring + rb * 32768);
        float4* dst4 = (float4*)hsm;
        float4 rreg[8];
#pragma unroll
        for (int q = 0; q < 8; ++q) rreg[q] = __ldcg(src4 + tid + 256 * q);

        unsigned long long d0[4] = {0ull, 0ull, 0ull, 0ull};
        unsigned long long d1[4] = {0ull, 0ull, 0ull, 0ull};

        for (int c = 0; c < 4; ++c) {
#pragma unroll
            for (int q = 0; q < 8; ++q)
                dst4[c * 2048 + tid + 256 * q] = rreg[q];
            if (c < 3) {
#pragma unroll
                for (int q = 0; q < 8; ++q)
                    rreg[q] = __ldcg(src4 + (c + 1) * 2048 + tid + 256 * q);
            }
            __syncthreads();
            const int kbeg = c << 7;
#pragma unroll 4
            for (int k = kbeg; k < kbeg + 128; k += 4) {
                const int k2 = k >> 1;
                U64F2 h01, h23;
                h01.f2 = *(const float2*)&hsm[(k2 * 64 + b) * 2];
                h23.f2 = *(const float2*)&hsm[((k2 + 1) * 64 + b) * 2];
#pragma unroll
                for (int g = 0; g < 4; ++g) {
                    F4U2 w0; w0.f4 = *(const float4*)&Wsm[(g * 8 + p) * 512 + k];
                    d0[g] = fma2(h01.u, w0.u2[0], d0[g]);
                    d0[g] = fma2(h23.u, w0.u2[1], d0[g]);
                    F4U2 w1; w1.f4 = *(const float4*)&Wsm[(g * 8 + p + 4) * 512 + k];
                    d1[g] = fma2(h01.u, w1.u2[0], d1[g]);
                    d1[g] = fma2(h23.u, w1.u2[1], d1[g]);
                }
            }
        }

        const bool mk = (x[b * 512 + t] != 0);
#pragma unroll
        for (int half = 0; half < 2; ++half) {
            const unsigned long long* dd = half ? d1 : d0;
            const float* bv = half ? bb1 : bb0;
            const int j = p + half * 4;
            const int u = u0 + j;
            const size_t xb = ((size_t)b * 512 + t) * 2048 + u;
            U64F2 e0, e1, e2, e3;
            e0.u = dd[0]; e1.u = dd[1]; e2.u = dd[2]; e3.u = dd[3];
            float s0 = __fadd_rn(e0.f2.x, e0.f2.y);
            float s1 = __fadd_rn(e1.f2.x, e1.f2.y);
            float s2 = __fadd_rn(e2.f2.x, e2.f2.y);
            float s3 = __fadd_rn(e3.f2.x, e3.f2.y);
            float zi = __fadd_rn(__fadd_rn(Xg[xb],        s0), bv[0]);
            float zf = __fadd_rn(__fadd_rn(Xg[xb + 512],  s1), bv[1]);
            float zg = __fadd_rn(__fadd_rn(Xg[xb + 1024], s2), bv[2]);
            float zo = __fadd_rn(__fadd_rn(Xg[xb + 1536], s3), bv[3]);
            float ii = sigmoid_xla(zi);
            float ff = sigmoid_xla(zf);
            float oo = sigmoid_xla(zo);
            float gg = tanh_xla(zg);
            float cold = csm[j * 64 + b];
            float cn = __fadd_rn(__fmul_rn(ff, cold), __fmul_rn(ii, gg));
            float hn = __fmul_rn(oo, tanh_xla(cn));
            float hold = hsm[((u >> 1) * 64 + b) * 2 + (u & 1)];
            float ck = mk ? cn : cold;
            float hk = mk ? hn : hold;
            csm[j * 64 + b] = ck;
            g_hid[((size_t)(t * 64 + b) * 2 + dir) * 512 + u] = mk ? hn : 0.f;
            ring[wbuf * 32768 + ((u >> 1) * 64 + b) * 2 + (u & 1)] = hk;
            if (s == 511) g_hT[b * 1024 + dir * 512 + u] = hk;
        }
        __threadfence();
        ++nbar;
        grid_barrier(nbar * NBLK);
    }
}

// ---------------- phase 3: emissions = hid @ fc_w.T + fc_b -------------------
// fp32 Kahan + exact product tail (fmaf residual); fp64 only for the 32-lane
// reduction. Error ~1e-13 — as good as the old fp64 path, no DFMA-pipe cost.
__global__ __launch_bounds__(256) void emis_kernel(const float* __restrict__ fcw,
                                                   const float* __restrict__ fcb) {
    const int warp = (blockIdx.x * 256 + threadIdx.x) >> 5;
    const int lane = threadIdx.x & 31;
    if (warp >= 32768) return;
    const float* hrow = g_hid + (size_t)warp * 1024;
    float s[12], c[12], ec[12];
#pragma unroll
    for (int j = 0; j < 12; ++j) { s[j] = 0.f; c[j] = 0.f; ec[j] = 0.f; }
    for (int k = lane; k < 1024; k += 32) {
        float hv = hrow[k];
#pragma unroll
        for (int j = 0; j < 12; ++j) {
            float w = __ldg(&fcw[j * 1024 + k]);
            float p = __fmul_rn(hv, w);
            float e = __fmaf_rn(hv, w, -p);          // exact product tail
            ec[j] = __fadd_rn(ec[j], e);
            float y = __fsub_rn(p, c[j]);            // Kahan
            float t = __fadd_rn(s[j], y);
            c[j] = __fsub_rn(__fsub_rn(t, s[j]), y);
            s[j] = t;
        }
    }
#pragma unroll
    for (int j = 0; j < 12; ++j) {
        double acc = (double)s[j] - (double)c[j] + (double)ec[j];
#pragma unroll
        for (int off = 16; off; off >>= 1)
            acc += __shfl_down_sync(0xffffffffu, acc, off);
        if (lane == 0)
            g_emis[(size_t)warp * 12 + j] = __fadd_rn((float)acc, fcb[j]);
    }
}

// ---------------- phase 4: class probs = softmax(hT @ fc2_w.T + fc2_b) -------
__global__ __launch_bounds__(32) void cls_kernel(const float* __restrict__ w2,
                                                 const float* __restrict__ b2,
                                                 float* __restrict__ out) {
    const int bb = blockIdx.x;
    const int lane = threadIdx.x;
    double acc[10];
#pragma unroll
    for (int j = 0; j < 10; ++j) acc[j] = 0.0;
    for (int k = lane; k < 1024; k += 32) {
        double hv = (double)g_hT[bb * 1024 + k];
#pragma unroll
        for (int j = 0; j < 10; ++j)
            acc[j] = fma(hv, (double)__ldg(&w2[j * 1024 + k]), acc[j]);
    }
#pragma unroll
    for (int j = 0; j < 10; ++j)
#pragma unroll
        for (int off = 16; off; off >>= 1)
            acc[j] += __shfl_down_sync(0xffffffffu, acc[j], off);
    if (lane == 0) {
        float z[10], mx = -1e30f, ssum = 0.f;
#pragma unroll
        for (int j = 0; j < 10; ++j) { z[j] = __fadd_rn((float)acc[j], b2[j]); mx = fmaxf(mx, z[j]); }
#pragma unroll
        for (int j = 0; j < 10; ++j) { z[j] = expf(z[j] - mx); ssum += z[j]; }
        float inv = 1.f / ssum;
#pragma unroll
        for (int j = 0; j < 10; ++j) out[64 + 32768 + bb * 10 + j] = z[j] * inv;
    }
}

// ---------------- phase 5: Viterbi — warp-synchronous, shfl-based ------------
__global__ __launch_bounds__(32) void vit_kernel(const int* __restrict__ x,
                                                 const float* __restrict__ trans,
                                                 float* __restrict__ out) {
    const int bb = blockIdx.x;
    const int lane = threadIdx.x;
    __shared__ float tr[144];
    __shared__ short bp[511][12];
    __shared__ short path[512];

    for (int i = lane; i < 144; i += 32) tr[i] = trans[i];
    __syncwarp();

    float tcol[12];
#pragma unroll
    for (int i = 0; i < 12; ++i) tcol[i] = (lane < 12) ? tr[i * 12 + lane] : 0.f;

    float alph = (lane < 12)
        ? __fadd_rn(tr[BOS * 12 + lane], g_emis[(size_t)(0 * 64 + bb) * 12 + lane])
        : -1e30f;

    // prefetch t=1
    float e_cur = (lane < 12) ? g_emis[(size_t)(1 * 64 + bb) * 12 + lane] : 0.f;
    int   v_cur = (x[bb * 512 + 1] != 0);

    for (int t = 1; t < 512; ++t) {
        float e_nxt = 0.f; int v_nxt = 0;
        if (t < 511) {
            e_nxt = (lane < 12) ? g_emis[(size_t)((t + 1) * 64 + bb) * 12 + lane] : 0.f;
            v_nxt = (x[bb * 512 + t + 1] != 0);
        }
        float best = -1e30f; int bi = 0;
#pragma unroll
        for (int i = 0; i < 12; ++i) {
            float ai = __shfl_sync(0xffffffffu, alph, i);
            float sc = __fadd_rn(ai, tcol[i]);
            if (sc > best) { best = sc; bi = i; }    // first-index tie-break
        }
        if (lane < 12) {
            alph = v_cur ? __fadd_rn(best, e_cur) : alph;
            bp[t - 1][lane] = v_cur ? (short)bi : (short)lane;
        }
        e_cur = e_nxt; v_cur = v_nxt;
    }
    __syncwarp();

    if (lane == 0) {
        float best = -1e30f; int bt = 0;
        float a[12];
        // collect alphas from lanes via shfl (lane0 executes; need warp-uniform shfl)
        ;
    }
    // gather final alphas to all lanes, then lane0 backtracks
    float fin = -1e30f;
    if (lane < 12) fin = __fadd_rn(alph, tr[lane * 12 + EOSx]);
    float best = -1e30f; int bt = 0;
#pragma unroll
    for (int i = 0; i < 12; ++i) {
        float fi = __shfl_sync(0xffffffffu, fin, i);
        if (fi > best) { best = fi; bt = i; }
    }
    if (lane == 0) {
        out[bb] = best;
        int tag = bt;
        for (int t = 511; t >= 1; --t) { path[t] = (short)tag; tag = bp[t - 1][tag]; }
        path[0] = (short)tag;
    }
    __syncwarp();
    for (int t = lane; t < 512; t += 32)
        out[64 + bb * 512 + t] = (x[bb * 512 + t] != 0) ? (float)path[t] : (float)PADTAG;
}

// ---------------- launcher ---------------------------------------------------
extern "C" void kernel_launch(void* const* d_in, const int* in_sizes, int n_in,
                              void* d_out, int out_size) {
    const int*   x      = (const int*)d_in[0];
    const float* emb    = (const float*)d_in[1];
    const float* w_ih_f = (const float*)d_in[2];
    const float* w_hh_f = (const float*)d_in[3];
    const float* b_f    = (const float*)d_in[4];
    const float* w_ih_b = (const float*)d_in[5];
    const float* w_hh_b = (const float*)d_in[6];
    const float* b_b    = (const float*)d_in[7];
    const float* fc_w   = (const float*)d_in[8];
    const float* fc_b   = (const float*)d_in[9];
    const float* fc2_w  = (const float*)d_in[10];
    const float* fc2_b  = (const float*)d_in[11];
    const float* trans  = (const float*)d_in[12];
    float* out = (float*)d_out;

    cudaFuncSetAttribute(lstm_kernel,
                         cudaFuncAttributeMaxDynamicSharedMemorySize, LSTM_SMEM);

    init_kernel<<<1, 32>>>();
    gemm_ih<<<dim3(32, 512, 2), 256>>>(x, emb, w_ih_f, w_ih_b);
    lstm_kernel<<<NBLK, 256, LSTM_SMEM>>>(x, w_hh_f, w_hh_b, b_f, b_b);
    emis_kernel<<<4096, 256>>>(fc_w, fc_b);
    cls_kernel<<<64, 32>>>(fc2_w, fc2_b, out);
    vit_kernel<<<64, 32>>>(x, trans, out);
}